// round 15
// baseline (speedup 1.0000x reference)
#include <cuda_runtime.h>
#include <cuda_fp16.h>
#include <math.h>
#include <stdint.h>

// ---------------------------------------------------------------------------
// Problem constants
// ---------------------------------------------------------------------------
constexpr int BATCH = 8192, INPUT = 4096, HIDDEN = 4096, CLASSES = 1000;
constexpr int NPAD = 1024;
constexpr int KDIM = 4096;
constexpr int BN = 128, BK = 64;
constexpr int NITER = KDIM / BK;           // 64
constexpr int STRIDE = 144;                // padded smem row bytes (128 data + 16 pad)
constexpr int TILE_BB = 128 * STRIDE;      // B tile bytes (128 rows)
constexpr int NSTAGES = 3;
constexpr int GTHREADS = 512;              // 16 warps -> 4 warps/SMSP

// MTILES = m16 tiles per warp (warp tile = MTILES*16 x 32; BM = MTILES*64)
// GEMM1: MTILES=2 (BM=128)  GEMM2: MTILES=1 (BM=64, fixes wave quantization)
constexpr int stage_bytes(int mtiles) {
    return 2 * (mtiles * 64 * STRIDE) + 2 * TILE_BB;
}
constexpr int DYN_SMEM1 = NSTAGES * stage_bytes(2);  // 221184
constexpr int DYN_SMEM2 = NSTAGES * stage_bytes(1);  // 165888

// ---------------------------------------------------------------------------
// Scratch (__device__ globals; allocation-free)
// ---------------------------------------------------------------------------
__device__ __align__(1024) __half g_x_s[2][(size_t)BATCH * INPUT];
__device__ __align__(1024) __half g_w1_s[2][(size_t)HIDDEN * INPUT];
__device__ __align__(1024) __half g_w2_s[2][(size_t)NPAD * INPUT];
__device__ __align__(1024) __half g_h_s[2][(size_t)BATCH * HIDDEN];
__device__ __align__(1024) float g_logits[(size_t)BATCH * NPAD];

// ---------------------------------------------------------------------------
// PTX helpers (sm_80-level only: cp.async, ldmatrix, mma.sync)
// ---------------------------------------------------------------------------
__device__ __forceinline__ uint32_t smem_u32(const void* p) {
    uint32_t a;
    asm("{ .reg .u64 t; cvta.to.shared.u64 t, %1; cvt.u32.u64 %0, t; }"
        : "=r"(a) : "l"(p));
    return a;
}
__device__ __forceinline__ void cp_async16(uint32_t dst, const void* src) {
    asm volatile("cp.async.cg.shared.global [%0], [%1], 16;"
                 :: "r"(dst), "l"(src) : "memory");
}
__device__ __forceinline__ void cp_commit() {
    asm volatile("cp.async.commit_group;" ::: "memory");
}
__device__ __forceinline__ void cp_wait0() {
    asm volatile("cp.async.wait_group 0;" ::: "memory");
}
__device__ __forceinline__ void cp_wait1() {
    asm volatile("cp.async.wait_group 1;" ::: "memory");
}
__device__ __forceinline__ void ldmatrix_x4(uint32_t& r0, uint32_t& r1,
                                            uint32_t& r2, uint32_t& r3, uint32_t a) {
    asm volatile("ldmatrix.sync.aligned.m8n8.x4.shared.b16 {%0,%1,%2,%3}, [%4];"
                 : "=r"(r0), "=r"(r1), "=r"(r2), "=r"(r3) : "r"(a));
}
__device__ __forceinline__ void mma_f16(float* d, const uint32_t* a, const uint32_t* b) {
    asm volatile(
        "mma.sync.aligned.m16n8k16.row.col.f32.f16.f16.f32 "
        "{%0,%1,%2,%3}, {%4,%5,%6,%7}, {%8,%9}, {%0,%1,%2,%3};"
        : "+f"(d[0]), "+f"(d[1]), "+f"(d[2]), "+f"(d[3])
        : "r"(a[0]), "r"(a[1]), "r"(a[2]), "r"(a[3]), "r"(b[0]), "r"(b[1]));
}

__device__ __forceinline__ uint32_t pack_f16(__half a, __half b) {
    __half2 t{a, b};
    uint32_t r;
    memcpy(&r, &t, 4);
    return r;
}
__device__ __forceinline__ void split2(float v, __half& h, __half& l) {
    h = __float2half_rn(v);
    l = __float2half_rn(v - __half2float(h));
}

// ---------------------------------------------------------------------------
// Merged split kernel: one launch handles x, w1, w2 (w2 zero-padded to NPAD).
// ---------------------------------------------------------------------------
__global__ __launch_bounds__(256)
void split2_all_kernel(const float4* __restrict__ x,
                       const float4* __restrict__ w1,
                       const float4* __restrict__ w2,
                       __half* __restrict__ xh, __half* __restrict__ xl,
                       __half* __restrict__ w1h, __half* __restrict__ w1l,
                       __half* __restrict__ w2h, __half* __restrict__ w2l,
                       int n4x, int n4w1, int n4w2p) {
    int i = blockIdx.x * blockDim.x + threadIdx.x;
    float4 v;
    __half* dh;
    __half* dl;
    int di;
    if (i < n4x) {
        v = x[i];
        dh = xh; dl = xl; di = i;
    } else if (i < n4x + n4w1) {
        di = i - n4x;
        v = w1[di];
        dh = w1h; dl = w1l;
    } else if (i < n4x + n4w1 + n4w2p) {
        di = i - n4x - n4w1;
        int row = di >> 10;  // INPUT/4 = 1024 float4 per row
        v = (row < CLASSES) ? w2[di] : make_float4(0.f, 0.f, 0.f, 0.f);
        dh = w2h; dl = w2l;
    } else {
        return;
    }
    __half h0, h1, h2, h3, l0, l1, l2, l3;
    split2(v.x, h0, l0);
    split2(v.y, h1, l1);
    split2(v.z, h2, l2);
    split2(v.w, h3, l3);
    ((uint2*)dh)[di] = make_uint2(pack_f16(h0, h1), pack_f16(h2, h3));
    ((uint2*)dl)[di] = make_uint2(pack_f16(l0, l1), pack_f16(l2, l3));
}

// ---------------------------------------------------------------------------
// Pipelined mma.sync fp16 GEMM, 2-way split, 3 products, DUAL accumulators:
//   acc  <- hi*hi ; acc2 <- hi*lo + lo*hi      (lo*lo dropped, ~2^-22)
// BM = MTILES*64, BN=128, BK=64, 3 stages + wait_group(1), 512 threads,
// warp tile (MTILES*16) x 32 in a 4x4 warp grid.
// MODE 0: out = relu(C + bias), re-split to 2 fp16 arrays (ld = HIDDEN)
// MODE 1: out = C + bias (fp32, ld = NPAD, bias guarded to biasN)
// ---------------------------------------------------------------------------
template <int MODE, int MTILES>
__global__ __launch_bounds__(GTHREADS, 1)
void gemm_kernel(const __half* __restrict__ A0,
                 const __half* __restrict__ A1,
                 const __half* __restrict__ B0,
                 const __half* __restrict__ B1,
                 const float* __restrict__ bias, int biasN,
                 __half* __restrict__ o_hi,
                 __half* __restrict__ o_lo,
                 float* __restrict__ o_f32) {
    constexpr int BM = MTILES * 64;
    constexpr int TILE_A = BM * STRIDE;
    constexpr int STAGE_B = 2 * TILE_A + 2 * TILE_BB;
    // smem tile offsets within a stage: A0, B0, A1, B1
    constexpr int oA0 = 0;
    constexpr int oB0 = TILE_A;
    constexpr int oA1 = TILE_A + TILE_BB;
    constexpr int oB1 = 2 * TILE_A + TILE_BB;

    extern __shared__ __align__(128) char smem[];
    const uint32_t smem_u = smem_u32(smem);

    const int tid = threadIdx.x;
    const int lane = tid & 31;
    const int wid = tid >> 5;       // 0..15
    const int warpRow = wid >> 2;   // 0..3
    const int warpCol = wid & 3;    // 0..3 -> 32 cols each
    const int blockM = blockIdx.y * BM;
    const int blockN = blockIdx.x * BN;

    constexpr size_t K2 = (size_t)KDIM * 2;

    // ---- loader: 512 threads; A: BM rows x 8 chunks (BM/64 per thread per
    // comp); B: 128 rows x 8 chunks (2 per thread per comp) ----
    const int lrow = tid >> 3;      // 0..63
    const int lch = tid & 7;        // 0..7 (16B chunk within 128B row)
    const char* gpA0 = (const char*)A0 + (size_t)(blockM + lrow) * K2 + lch * 16;
    const char* gpA1 = (const char*)A1 + (size_t)(blockM + lrow) * K2 + lch * 16;
    const char* gpB0 = (const char*)B0 + (size_t)(blockN + lrow) * K2 + lch * 16;
    const char* gpB1 = (const char*)B1 + (size_t)(blockN + lrow) * K2 + lch * 16;
    const uint32_t sdst0 = lrow * STRIDE + lch * 16;

    auto load_stage = [&](int bufb) {
        const uint32_t sb = smem_u + bufb * STAGE_B + sdst0;
        #pragma unroll
        for (int j = 0; j < MTILES; j++) {
            cp_async16(sb + oA0 + j * (64 * STRIDE), gpA0 + (size_t)j * 64 * K2);
            cp_async16(sb + oA1 + j * (64 * STRIDE), gpA1 + (size_t)j * 64 * K2);
        }
        cp_async16(sb + oB0, gpB0);
        cp_async16(sb + oB0 + 64 * STRIDE, gpB0 + (size_t)64 * K2);
        cp_async16(sb + oB1, gpB1);
        cp_async16(sb + oB1 + 64 * STRIDE, gpB1 + (size_t)64 * K2);
        gpA0 += BK * 2; gpA1 += BK * 2; gpB0 += BK * 2; gpB1 += BK * 2;
        cp_commit();
    };

    float acc[MTILES][4][4];   // main: hi*hi
    float acc2[MTILES][4][4];  // corrections: hi*lo + lo*hi
    #pragma unroll
    for (int mt = 0; mt < MTILES; mt++)
        #pragma unroll
        for (int nt = 0; nt < 4; nt++)
            #pragma unroll
            for (int e = 0; e < 4; e++) { acc[mt][nt][e] = 0.0f; acc2[mt][nt][e] = 0.0f; }

    // ldmatrix per-lane address components
    const int rA = ((lane >> 3) & 1) * 8 + (lane & 7);
    const int cA = (lane >> 4);
    const int rB = (lane >> 4) * 8 + (lane & 7);
    const int cB = (lane >> 3) & 1;

    // prologue: stages 0, 1
    load_stage(0);
    load_stage(1);

    for (int it = 0; it < NITER; it++) {
        if (it + 1 < NITER) cp_wait1(); else cp_wait0();
        __syncthreads();
        if (it + 2 < NITER) load_stage((it + 2) % NSTAGES);

        const uint32_t stage = smem_u + (it % NSTAGES) * STAGE_B;
        #pragma unroll
        for (int kh = 0; kh < 4; kh++) {
            // A fragments: 2 comps x MTILES m16 tiles
            uint32_t aF[2][MTILES][4];
            #pragma unroll
            for (int t = 0; t < 2; t++) {
                const uint32_t Abase = stage + (t ? oA1 : oA0);
                #pragma unroll
                for (int mt = 0; mt < MTILES; mt++) {
                    uint32_t addr = Abase + (warpRow * (MTILES * 16) + mt * 16 + rA) * STRIDE +
                                    (kh * 2 + cA) * 16;
                    ldmatrix_x4(aF[t][mt][0], aF[t][mt][1], aF[t][mt][2], aF[t][mt][3], addr);
                }
            }
            // B fragments: 2 comps x 4 n8 tiles
            uint32_t bF[2][4][2];
            #pragma unroll
            for (int t = 0; t < 2; t++) {
                const uint32_t Bbase = stage + (t ? oB1 : oB0);
                #pragma unroll
                for (int pr = 0; pr < 2; pr++) {
                    uint32_t addr = Bbase + (warpCol * 32 + pr * 16 + rB) * STRIDE +
                                    (kh * 2 + cB) * 16;
                    uint32_t r0, r1, r2, r3;
                    ldmatrix_x4(r0, r1, r2, r3, addr);
                    bF[t][pr * 2 + 0][0] = r0; bF[t][pr * 2 + 0][1] = r1;
                    bF[t][pr * 2 + 1][0] = r2; bF[t][pr * 2 + 1][1] = r3;
                }
            }
            // hi*hi -> acc ; hi*lo + lo*hi -> acc2 (grouped, r10 order)
            #pragma unroll
            for (int mt = 0; mt < MTILES; mt++)
                #pragma unroll
                for (int nt = 0; nt < 4; nt++)
                    mma_f16(acc[mt][nt], aF[0][mt], bF[0][nt]);
            #pragma unroll
            for (int mt = 0; mt < MTILES; mt++)
                #pragma unroll
                for (int nt = 0; nt < 4; nt++)
                    mma_f16(acc2[mt][nt], aF[0][mt], bF[1][nt]);
            #pragma unroll
            for (int mt = 0; mt < MTILES; mt++)
                #pragma unroll
                for (int nt = 0; nt < 4; nt++)
                    mma_f16(acc2[mt][nt], aF[1][mt], bF[0][nt]);
        }
    }

    // ---- epilogue ----
    const int gr = lane >> 2;         // row within 8
    const int cc = (lane & 3) * 2;    // col pair

    #pragma unroll
    for (int mt = 0; mt < MTILES; mt++) {
        #pragma unroll
        for (int nt = 0; nt < 4; nt++) {
            float d[4];
            #pragma unroll
            for (int e = 0; e < 4; e++) d[e] = acc[mt][nt][e] + acc2[mt][nt][e];
            const int col = blockN + warpCol * 32 + nt * 8 + cc;
            const int row0 = blockM + warpRow * (MTILES * 16) + mt * 16 + gr;
            float bv0, bv1;
            if (MODE == 0) {
                bv0 = bias[col];
                bv1 = bias[col + 1];
            } else {
                bv0 = (col < biasN) ? bias[col] : 0.0f;
                bv1 = (col + 1 < biasN) ? bias[col + 1] : 0.0f;
            }
            if (MODE == 0) {
                #pragma unroll
                for (int h = 0; h < 2; h++) {
                    const int row = row0 + h * 8;
                    float v0 = fmaxf(d[2 * h + 0] + bv0, 0.0f);
                    float v1 = fmaxf(d[2 * h + 1] + bv1, 0.0f);
                    __half h0, l0, h1, l1;
                    split2(v0, h0, l0);
                    split2(v1, h1, l1);
                    size_t off = (size_t)row * HIDDEN + col;
                    *(uint32_t*)(o_hi + off) = pack_f16(h0, h1);
                    *(uint32_t*)(o_lo + off) = pack_f16(l0, l1);
                }
            } else {
                #pragma unroll
                for (int h = 0; h < 2; h++) {
                    const int row = row0 + h * 8;
                    float2 v;
                    v.x = d[2 * h + 0] + bv0;
                    v.y = d[2 * h + 1] + bv1;
                    *(float2*)(o_f32 + (size_t)row * NPAD + col) = v;
                }
            }
        }
    }
}

// ---------------------------------------------------------------------------
// Row softmax (reads NPAD-strided logits, first CLASSES cols)
// ---------------------------------------------------------------------------
__inline__ __device__ float warpMax(float v) {
    #pragma unroll
    for (int o = 16; o > 0; o >>= 1) v = fmaxf(v, __shfl_xor_sync(0xffffffffu, v, o));
    return v;
}
__inline__ __device__ float warpSum(float v) {
    #pragma unroll
    for (int o = 16; o > 0; o >>= 1) v += __shfl_xor_sync(0xffffffffu, v, o);
    return v;
}

__global__ __launch_bounds__(256)
void softmax_kernel(const float* __restrict__ logits, float* __restrict__ out) {
    const int row = blockIdx.x;
    const float* lp = logits + (size_t)row * NPAD;
    float* op = out + (size_t)row * CLASSES;

    const int tid = threadIdx.x, lane = tid & 31, warp = tid >> 5;
    __shared__ float red[8];

    float v[4];
    int idx[4], cnt = 0;
    for (int i = tid; i < CLASSES; i += 256) { v[cnt] = lp[i]; idx[cnt] = i; cnt++; }

    float m = -INFINITY;
    for (int t = 0; t < cnt; t++) m = fmaxf(m, v[t]);
    m = warpMax(m);
    if (lane == 0) red[warp] = m;
    __syncthreads();
    m = (lane < 8) ? red[lane] : -INFINITY;
    m = warpMax(m);
    m = __shfl_sync(0xffffffffu, m, 0);

    float s = 0.0f;
    for (int t = 0; t < cnt; t++) { v[t] = __expf(v[t] - m); s += v[t]; }
    s = warpSum(s);
    __syncthreads();
    if (lane == 0) red[warp] = s;
    __syncthreads();
    s = (lane < 8) ? red[lane] : 0.0f;
    s = warpSum(s);
    s = __shfl_sync(0xffffffffu, s, 0);

    const float inv = 1.0f / s;
    for (int t = 0; t < cnt; t++) op[idx[t]] = v[t] * inv;
}

// ---------------------------------------------------------------------------
// Host launch
// ---------------------------------------------------------------------------
extern "C" void kernel_launch(void* const* d_in, const int* in_sizes, int n_in,
                              void* d_out, int out_size) {
    const float* x  = (const float*)d_in[0];
    const float* w1 = (const float*)d_in[1];
    const float* b1 = (const float*)d_in[2];
    const float* w2 = (const float*)d_in[3];
    const float* b2 = (const float*)d_in[4];
    float* out = (float*)d_out;

    __half *xs, *w1s, *w2s, *hs;
    float* logits;
    cudaGetSymbolAddress((void**)&xs,  g_x_s);
    cudaGetSymbolAddress((void**)&w1s, g_w1_s);
    cudaGetSymbolAddress((void**)&w2s, g_w2_s);
    cudaGetSymbolAddress((void**)&hs,  g_h_s);
    cudaGetSymbolAddress((void**)&logits, g_logits);

    const size_t XN  = (size_t)BATCH * INPUT;
    const size_t W1N = (size_t)HIDDEN * INPUT;
    const size_t W2N = (size_t)NPAD * INPUT;
    const size_t HN  = (size_t)BATCH * HIDDEN;

    __half* x_c[2]  = {xs, xs + XN};
    __half* w1_c[2] = {w1s, w1s + W1N};
    __half* w2_c[2] = {w2s, w2s + W2N};
    __half* h_c[2]  = {hs, hs + HN};

    // One merged split launch for x, w1, w2
    {
        int n4x = (int)(XN / 4);
        int n4w1 = (int)(W1N / 4);
        int n4w2p = (int)(W2N / 4);
        int total = n4x + n4w1 + n4w2p;
        split2_all_kernel<<<(total + 255) / 256, 256>>>(
            (const float4*)x, (const float4*)w1, (const float4*)w2,
            x_c[0], x_c[1], w1_c[0], w1_c[1], w2_c[0], w2_c[1],
            n4x, n4w1, n4w2p);
    }

    cudaFuncSetAttribute(gemm_kernel<0, 2>, cudaFuncAttributeMaxDynamicSharedMemorySize, DYN_SMEM1);
    cudaFuncSetAttribute(gemm_kernel<1, 1>, cudaFuncAttributeMaxDynamicSharedMemorySize, DYN_SMEM2);

    // GEMM1: hidden = relu(x @ w1^T + b1), re-split into 2 fp16 components
    // BM=128 (MTILES=2): grid 32 x 64 = 2048 CTAs
    {
        dim3 grid(HIDDEN / BN, BATCH / 128);
        gemm_kernel<0, 2><<<grid, GTHREADS, DYN_SMEM1>>>(
            x_c[0], x_c[1], w1_c[0], w1_c[1],
            b1, HIDDEN, h_c[0], h_c[1], nullptr);
    }
    // GEMM2: logits = hidden @ w2^T + b2 (fp32, NPAD-wide scratch)
    // BM=64 (MTILES=1): grid 8 x 128 = 1024 CTAs -> 7 waves (vs 4 partial)
    {
        dim3 grid(NPAD / BN, BATCH / 64);
        gemm_kernel<1, 1><<<grid, GTHREADS, DYN_SMEM2>>>(
            h_c[0], h_c[1], w2_c[0], w2_c[1],
            b2, CLASSES, nullptr, nullptr, logits);
    }
    softmax_kernel<<<BATCH, 256>>>(logits, out);
}

// round 16
// speedup vs baseline: 1.0593x; 1.0593x over previous
#include <cuda_runtime.h>
#include <cuda_fp16.h>
#include <math.h>
#include <stdint.h>

// ---------------------------------------------------------------------------
// Problem constants
// ---------------------------------------------------------------------------
constexpr int BATCH = 8192, INPUT = 4096, HIDDEN = 4096, CLASSES = 1000;
constexpr int NPAD = 1024;
constexpr int KDIM = 4096;
constexpr int BM = 128, BN = 128, BK = 64;
constexpr int STRIDE = 144;                // padded smem row bytes (128 data + 16 pad)
constexpr int TILE_B = 128 * STRIDE;       // 18432 bytes per tile
constexpr int STAGE_B = 4 * TILE_B;        // 73728 (A0,B0,A1,B1)
constexpr int NSTAGES = 3;
constexpr int DYN_SMEM = NSTAGES * STAGE_B;  // 221184
constexpr int GTHREADS = 512;              // 16 warps -> 4 warps/SMSP

// ---------------------------------------------------------------------------
// Scratch (__device__ globals; allocation-free)
// ---------------------------------------------------------------------------
__device__ __align__(1024) __half g_x_s[2][(size_t)BATCH * INPUT];
__device__ __align__(1024) __half g_w1_s[2][(size_t)HIDDEN * INPUT];
__device__ __align__(1024) __half g_w2_s[2][(size_t)NPAD * INPUT];
__device__ __align__(1024) __half g_h_s[2][(size_t)BATCH * HIDDEN];
__device__ __align__(1024) float g_logits[2][(size_t)BATCH * NPAD];  // split-K planes

// ---------------------------------------------------------------------------
// PTX helpers (sm_80-level only: cp.async, ldmatrix, mma.sync)
// ---------------------------------------------------------------------------
__device__ __forceinline__ uint32_t smem_u32(const void* p) {
    uint32_t a;
    asm("{ .reg .u64 t; cvta.to.shared.u64 t, %1; cvt.u32.u64 %0, t; }"
        : "=r"(a) : "l"(p));
    return a;
}
__device__ __forceinline__ void cp_async16(uint32_t dst, const void* src) {
    asm volatile("cp.async.cg.shared.global [%0], [%1], 16;"
                 :: "r"(dst), "l"(src) : "memory");
}
__device__ __forceinline__ void cp_commit() {
    asm volatile("cp.async.commit_group;" ::: "memory");
}
__device__ __forceinline__ void cp_wait0() {
    asm volatile("cp.async.wait_group 0;" ::: "memory");
}
__device__ __forceinline__ void cp_wait1() {
    asm volatile("cp.async.wait_group 1;" ::: "memory");
}
__device__ __forceinline__ void ldmatrix_x4(uint32_t& r0, uint32_t& r1,
                                            uint32_t& r2, uint32_t& r3, uint32_t a) {
    asm volatile("ldmatrix.sync.aligned.m8n8.x4.shared.b16 {%0,%1,%2,%3}, [%4];"
                 : "=r"(r0), "=r"(r1), "=r"(r2), "=r"(r3) : "r"(a));
}
__device__ __forceinline__ void mma_f16(float* d, const uint32_t* a, const uint32_t* b) {
    asm volatile(
        "mma.sync.aligned.m16n8k16.row.col.f32.f16.f16.f32 "
        "{%0,%1,%2,%3}, {%4,%5,%6,%7}, {%8,%9}, {%0,%1,%2,%3};"
        : "+f"(d[0]), "+f"(d[1]), "+f"(d[2]), "+f"(d[3])
        : "r"(a[0]), "r"(a[1]), "r"(a[2]), "r"(a[3]), "r"(b[0]), "r"(b[1]));
}

__device__ __forceinline__ uint32_t pack_f16(__half a, __half b) {
    __half2 t{a, b};
    uint32_t r;
    memcpy(&r, &t, 4);
    return r;
}
__device__ __forceinline__ void split2(float v, __half& h, __half& l) {
    h = __float2half_rn(v);
    l = __float2half_rn(v - __half2float(h));
}

// ---------------------------------------------------------------------------
// Merged split kernel: one launch handles x, w1, w2 (w2 zero-padded to NPAD).
// ---------------------------------------------------------------------------
__global__ __launch_bounds__(256)
void split2_all_kernel(const float4* __restrict__ x,
                       const float4* __restrict__ w1,
                       const float4* __restrict__ w2,
                       __half* __restrict__ xh, __half* __restrict__ xl,
                       __half* __restrict__ w1h, __half* __restrict__ w1l,
                       __half* __restrict__ w2h, __half* __restrict__ w2l,
                       int n4x, int n4w1, int n4w2p) {
    int i = blockIdx.x * blockDim.x + threadIdx.x;
    float4 v;
    __half* dh;
    __half* dl;
    int di;
    if (i < n4x) {
        v = x[i];
        dh = xh; dl = xl; di = i;
    } else if (i < n4x + n4w1) {
        di = i - n4x;
        v = w1[di];
        dh = w1h; dl = w1l;
    } else if (i < n4x + n4w1 + n4w2p) {
        di = i - n4x - n4w1;
        int row = di >> 10;  // INPUT/4 = 1024 float4 per row
        v = (row < CLASSES) ? w2[di] : make_float4(0.f, 0.f, 0.f, 0.f);
        dh = w2h; dl = w2l;
    } else {
        return;
    }
    __half h0, h1, h2, h3, l0, l1, l2, l3;
    split2(v.x, h0, l0);
    split2(v.y, h1, l1);
    split2(v.z, h2, l2);
    split2(v.w, h3, l3);
    ((uint2*)dh)[di] = make_uint2(pack_f16(h0, h1), pack_f16(h2, h3));
    ((uint2*)dl)[di] = make_uint2(pack_f16(l0, l1), pack_f16(l2, l3));
}

// ---------------------------------------------------------------------------
// Pipelined mma.sync fp16 GEMM, 2-way split, 3 products, DUAL accumulators:
//   acc  <- hi*hi ; acc2 <- hi*lo + lo*hi      (lo*lo dropped, ~2^-22)
// 128x128 CTA tile, BK=64, 3 stages + wait_group(1), 512 threads (4
// warps/SMSP), 32x32 warp tiles, grouped products (round-10/14 config).
// Split-K via blockIdx.z: covers K range [z*kspan, (z+1)*kspan); MODE 1
// writes to logits plane z (bias added only by z==0).
// MODE 0: out = relu(C + bias), re-split to 2 fp16 arrays (ld = HIDDEN)
// MODE 1: out = C (+bias if z==0) fp32 to o_f32 + z*BATCH*NPAD (ld = NPAD)
// ---------------------------------------------------------------------------
template <int MODE>
__global__ __launch_bounds__(GTHREADS, 1)
void gemm_kernel(const __half* __restrict__ A0,
                 const __half* __restrict__ A1,
                 const __half* __restrict__ B0,
                 const __half* __restrict__ B1,
                 const float* __restrict__ bias, int biasN,
                 __half* __restrict__ o_hi,
                 __half* __restrict__ o_lo,
                 float* __restrict__ o_f32,
                 int kspan) {
    extern __shared__ __align__(128) char smem[];
    const uint32_t smem_u = smem_u32(smem);

    const int tid = threadIdx.x;
    const int lane = tid & 31;
    const int wid = tid >> 5;       // 0..15
    const int warpRow = wid >> 2;   // 0..3 -> 32 rows each
    const int warpCol = wid & 3;    // 0..3 -> 32 cols each
    const int blockM = blockIdx.y * BM;
    const int blockN = blockIdx.x * BN;
    const int kz = blockIdx.z;
    const int kbase = kz * kspan;          // element offset in K
    const int niter = kspan / BK;

    constexpr size_t K2 = (size_t)KDIM * 2;

    // ---- loader: 512 threads, 8 cp.async each (2 rows x 4 matrices) ----
    const int lrow = tid >> 3;      // 0..63
    const int lch = tid & 7;        // 0..7 (16B chunk within 128B row)
    const char* gp[4];
    gp[0] = (const char*)A0 + (size_t)(blockM + lrow) * K2 + (size_t)kbase * 2 + lch * 16;
    gp[1] = (const char*)B0 + (size_t)(blockN + lrow) * K2 + (size_t)kbase * 2 + lch * 16;
    gp[2] = (const char*)A1 + (size_t)(blockM + lrow) * K2 + (size_t)kbase * 2 + lch * 16;
    gp[3] = (const char*)B1 + (size_t)(blockN + lrow) * K2 + (size_t)kbase * 2 + lch * 16;
    const uint32_t sdst0 = lrow * STRIDE + lch * 16;

    auto load_stage = [&](int bufb) {
        const uint32_t sb = smem_u + bufb * STAGE_B + sdst0;
        #pragma unroll
        for (int mc = 0; mc < 4; mc++) {
            const char* g = gp[mc];
            cp_async16(sb + mc * TILE_B, g);
            cp_async16(sb + mc * TILE_B + 64 * STRIDE, g + (size_t)64 * K2);
            gp[mc] = g + BK * 2;   // advance K by BK elements
        }
        cp_commit();
    };

    float acc[2][4][4];   // main: hi*hi   (2 m16 tiles x 4 n8 tiles)
    float acc2[2][4][4];  // corrections: hi*lo + lo*hi
    #pragma unroll
    for (int mt = 0; mt < 2; mt++)
        #pragma unroll
        for (int nt = 0; nt < 4; nt++)
            #pragma unroll
            for (int e = 0; e < 4; e++) { acc[mt][nt][e] = 0.0f; acc2[mt][nt][e] = 0.0f; }

    // ldmatrix per-lane address components
    const int rA = ((lane >> 3) & 1) * 8 + (lane & 7);
    const int cA = (lane >> 4);
    const int rB = (lane >> 4) * 8 + (lane & 7);
    const int cB = (lane >> 3) & 1;

    // prologue: stages 0, 1
    load_stage(0);
    load_stage(1);

    for (int it = 0; it < niter; it++) {
        if (it + 1 < niter) cp_wait1(); else cp_wait0();
        __syncthreads();
        // issue stage it+2 into buffer (it+2)%3 == (it-1)%3 (consumed at it-1;
        // safe: all warps passed the barrier above after finishing it-1)
        if (it + 2 < niter) load_stage((it + 2) % NSTAGES);

        const uint32_t stage = smem_u + (it % NSTAGES) * STAGE_B;
        #pragma unroll
        for (int kh = 0; kh < 4; kh++) {
            // A fragments: 2 comps x 2 m16 tiles
            uint32_t aF[2][2][4];
            #pragma unroll
            for (int t = 0; t < 2; t++) {
                const uint32_t Abase = stage + (2 * t) * TILE_B;
                #pragma unroll
                for (int mt = 0; mt < 2; mt++) {
                    uint32_t addr = Abase + (warpRow * 32 + mt * 16 + rA) * STRIDE +
                                    (kh * 2 + cA) * 16;
                    ldmatrix_x4(aF[t][mt][0], aF[t][mt][1], aF[t][mt][2], aF[t][mt][3], addr);
                }
            }
            // B fragments: 2 comps x 4 n8 tiles
            uint32_t bF[2][4][2];
            #pragma unroll
            for (int t = 0; t < 2; t++) {
                const uint32_t Bbase = stage + (2 * t + 1) * TILE_B;
                #pragma unroll
                for (int pr = 0; pr < 2; pr++) {
                    uint32_t addr = Bbase + (warpCol * 32 + pr * 16 + rB) * STRIDE +
                                    (kh * 2 + cB) * 16;
                    uint32_t r0, r1, r2, r3;
                    ldmatrix_x4(r0, r1, r2, r3, addr);
                    bF[t][pr * 2 + 0][0] = r0; bF[t][pr * 2 + 0][1] = r1;
                    bF[t][pr * 2 + 1][0] = r2; bF[t][pr * 2 + 1][1] = r3;
                }
            }
            // hi*hi -> acc ; hi*lo + lo*hi -> acc2 (grouped, r10 order)
            #pragma unroll
            for (int mt = 0; mt < 2; mt++)
                #pragma unroll
                for (int nt = 0; nt < 4; nt++)
                    mma_f16(acc[mt][nt], aF[0][mt], bF[0][nt]);
            #pragma unroll
            for (int mt = 0; mt < 2; mt++)
                #pragma unroll
                for (int nt = 0; nt < 4; nt++)
                    mma_f16(acc2[mt][nt], aF[0][mt], bF[1][nt]);
            #pragma unroll
            for (int mt = 0; mt < 2; mt++)
                #pragma unroll
                for (int nt = 0; nt < 4; nt++)
                    mma_f16(acc2[mt][nt], aF[1][mt], bF[0][nt]);
        }
    }

    // ---- epilogue ----
    const int gr = lane >> 2;         // row within 8
    const int cc = (lane & 3) * 2;    // col pair
    float* o_plane = o_f32 + (size_t)kz * BATCH * NPAD;

    #pragma unroll
    for (int mt = 0; mt < 2; mt++) {
        #pragma unroll
        for (int nt = 0; nt < 4; nt++) {
            float d[4];
            #pragma unroll
            for (int e = 0; e < 4; e++) d[e] = acc[mt][nt][e] + acc2[mt][nt][e];
            const int col = blockN + warpCol * 32 + nt * 8 + cc;
            const int row0 = blockM + warpRow * 32 + mt * 16 + gr;
            float bv0, bv1;
            if (MODE == 0) {
                bv0 = bias[col];
                bv1 = bias[col + 1];
            } else {
                // bias only from the z==0 plane
                bv0 = (kz == 0 && col < biasN) ? bias[col] : 0.0f;
                bv1 = (kz == 0 && col + 1 < biasN) ? bias[col + 1] : 0.0f;
            }
            if (MODE == 0) {
                #pragma unroll
                for (int h = 0; h < 2; h++) {
                    const int row = row0 + h * 8;
                    float v0 = fmaxf(d[2 * h + 0] + bv0, 0.0f);
                    float v1 = fmaxf(d[2 * h + 1] + bv1, 0.0f);
                    __half h0, l0, h1, l1;
                    split2(v0, h0, l0);
                    split2(v1, h1, l1);
                    size_t off = (size_t)row * HIDDEN + col;
                    *(uint32_t*)(o_hi + off) = pack_f16(h0, h1);
                    *(uint32_t*)(o_lo + off) = pack_f16(l0, l1);
                }
            } else {
                #pragma unroll
                for (int h = 0; h < 2; h++) {
                    const int row = row0 + h * 8;
                    float2 v;
                    v.x = d[2 * h + 0] + bv0;
                    v.y = d[2 * h + 1] + bv1;
                    *(float2*)(o_plane + (size_t)row * NPAD + col) = v;
                }
            }
        }
    }
}

// ---------------------------------------------------------------------------
// Row softmax over two split-K logits planes (summed on load)
// ---------------------------------------------------------------------------
__inline__ __device__ float warpMax(float v) {
    #pragma unroll
    for (int o = 16; o > 0; o >>= 1) v = fmaxf(v, __shfl_xor_sync(0xffffffffu, v, o));
    return v;
}
__inline__ __device__ float warpSum(float v) {
    #pragma unroll
    for (int o = 16; o > 0; o >>= 1) v += __shfl_xor_sync(0xffffffffu, v, o);
    return v;
}

__global__ __launch_bounds__(256)
void softmax_kernel(const float* __restrict__ logits0,
                    const float* __restrict__ logits1,
                    float* __restrict__ out) {
    const int row = blockIdx.x;
    const float* lp0 = logits0 + (size_t)row * NPAD;
    const float* lp1 = logits1 + (size_t)row * NPAD;
    float* op = out + (size_t)row * CLASSES;

    const int tid = threadIdx.x, lane = tid & 31, warp = tid >> 5;
    __shared__ float red[8];

    float v[4];
    int idx[4], cnt = 0;
    for (int i = tid; i < CLASSES; i += 256) {
        v[cnt] = lp0[i] + lp1[i];
        idx[cnt] = i;
        cnt++;
    }

    float m = -INFINITY;
    for (int t = 0; t < cnt; t++) m = fmaxf(m, v[t]);
    m = warpMax(m);
    if (lane == 0) red[warp] = m;
    __syncthreads();
    m = (lane < 8) ? red[lane] : -INFINITY;
    m = warpMax(m);
    m = __shfl_sync(0xffffffffu, m, 0);

    float s = 0.0f;
    for (int t = 0; t < cnt; t++) { v[t] = __expf(v[t] - m); s += v[t]; }
    s = warpSum(s);
    __syncthreads();
    if (lane == 0) red[warp] = s;
    __syncthreads();
    s = (lane < 8) ? red[lane] : 0.0f;
    s = warpSum(s);
    s = __shfl_sync(0xffffffffu, s, 0);

    const float inv = 1.0f / s;
    for (int t = 0; t < cnt; t++) op[idx[t]] = v[t] * inv;
}

// ---------------------------------------------------------------------------
// Host launch
// ---------------------------------------------------------------------------
extern "C" void kernel_launch(void* const* d_in, const int* in_sizes, int n_in,
                              void* d_out, int out_size) {
    const float* x  = (const float*)d_in[0];
    const float* w1 = (const float*)d_in[1];
    const float* b1 = (const float*)d_in[2];
    const float* w2 = (const float*)d_in[3];
    const float* b2 = (const float*)d_in[4];
    float* out = (float*)d_out;

    __half *xs, *w1s, *w2s, *hs;
    float* logits;
    cudaGetSymbolAddress((void**)&xs,  g_x_s);
    cudaGetSymbolAddress((void**)&w1s, g_w1_s);
    cudaGetSymbolAddress((void**)&w2s, g_w2_s);
    cudaGetSymbolAddress((void**)&hs,  g_h_s);
    cudaGetSymbolAddress((void**)&logits, g_logits);

    const size_t XN  = (size_t)BATCH * INPUT;
    const size_t W1N = (size_t)HIDDEN * INPUT;
    const size_t W2N = (size_t)NPAD * INPUT;
    const size_t HN  = (size_t)BATCH * HIDDEN;
    const size_t LN  = (size_t)BATCH * NPAD;

    __half* x_c[2]  = {xs, xs + XN};
    __half* w1_c[2] = {w1s, w1s + W1N};
    __half* w2_c[2] = {w2s, w2s + W2N};
    __half* h_c[2]  = {hs, hs + HN};

    // One merged split launch for x, w1, w2
    {
        int n4x = (int)(XN / 4);
        int n4w1 = (int)(W1N / 4);
        int n4w2p = (int)(W2N / 4);
        int total = n4x + n4w1 + n4w2p;
        split2_all_kernel<<<(total + 255) / 256, 256>>>(
            (const float4*)x, (const float4*)w1, (const float4*)w2,
            x_c[0], x_c[1], w1_c[0], w1_c[1], w2_c[0], w2_c[1],
            n4x, n4w1, n4w2p);
    }

    cudaFuncSetAttribute(gemm_kernel<0>, cudaFuncAttributeMaxDynamicSharedMemorySize, DYN_SMEM);
    cudaFuncSetAttribute(gemm_kernel<1>, cudaFuncAttributeMaxDynamicSharedMemorySize, DYN_SMEM);

    // GEMM1: hidden = relu(x @ w1^T + b1), re-split into 2 fp16 components
    // grid 32 x 64 x 1, full K
    {
        dim3 grid(HIDDEN / BN, BATCH / BM, 1);
        gemm_kernel<0><<<grid, GTHREADS, DYN_SMEM>>>(
            x_c[0], x_c[1], w1_c[0], w1_c[1],
            b1, HIDDEN, h_c[0], h_c[1], nullptr, KDIM);
    }
    // GEMM2: logits = hidden @ w2^T + b2, split-K=2 into two planes
    // grid 8 x 64 x 2 = 1024 CTAs -> ~6.9 waves (vs 3.46 with 46% tail)
    {
        dim3 grid(NPAD / BN, BATCH / BM, 2);
        gemm_kernel<1><<<grid, GTHREADS, DYN_SMEM>>>(
            h_c[0], h_c[1], w2_c[0], w2_c[1],
            b2, CLASSES, nullptr, nullptr, logits, KDIM / 2);
    }
    // Softmax over summed planes
    softmax_kernel<<<BATCH, 256>>>(logits, logits + LN, out);
}

// round 17
// speedup vs baseline: 1.0628x; 1.0033x over previous
#include <cuda_runtime.h>
#include <cuda_fp16.h>
#include <math.h>
#include <stdint.h>

// ---------------------------------------------------------------------------
// Problem constants
// ---------------------------------------------------------------------------
constexpr int BATCH = 8192, INPUT = 4096, HIDDEN = 4096, CLASSES = 1000;
constexpr int NPAD = 1024;
constexpr int KDIM = 4096;
constexpr int BM = 128, BN = 128, BK = 64;
constexpr int STRIDE = 144;                // padded smem row bytes (128 data + 16 pad)
constexpr int TILE_B = 128 * STRIDE;       // 18432 bytes per tile
constexpr int STAGE_B = 4 * TILE_B;        // 73728 (A0,B0,A1,B1)
constexpr int NSTAGES = 3;
constexpr int DYN_SMEM = NSTAGES * STAGE_B;  // 221184
constexpr int GTHREADS = 512;              // 16 warps -> 4 warps/SMSP

// ---------------------------------------------------------------------------
// Scratch (__device__ globals; allocation-free)
// ---------------------------------------------------------------------------
__device__ __align__(1024) __half g_x_s[2][(size_t)BATCH * INPUT];
__device__ __align__(1024) __half g_w1_s[2][(size_t)HIDDEN * INPUT];
__device__ __align__(1024) __half g_w2_s[2][(size_t)NPAD * INPUT];
__device__ __align__(1024) __half g_h_s[2][(size_t)BATCH * HIDDEN];
__device__ __align__(1024) float g_logits[2][(size_t)BATCH * NPAD];  // split-K planes

// ---------------------------------------------------------------------------
// PTX helpers (sm_80-level only: cp.async, ldmatrix, mma.sync)
// ---------------------------------------------------------------------------
__device__ __forceinline__ uint32_t smem_u32(const void* p) {
    uint32_t a;
    asm("{ .reg .u64 t; cvta.to.shared.u64 t, %1; cvt.u32.u64 %0, t; }"
        : "=r"(a) : "l"(p));
    return a;
}
__device__ __forceinline__ void cp_async16(uint32_t dst, const void* src) {
    asm volatile("cp.async.cg.shared.global [%0], [%1], 16;"
                 :: "r"(dst), "l"(src) : "memory");
}
__device__ __forceinline__ void cp_commit() {
    asm volatile("cp.async.commit_group;" ::: "memory");
}
__device__ __forceinline__ void cp_wait0() {
    asm volatile("cp.async.wait_group 0;" ::: "memory");
}
__device__ __forceinline__ void cp_wait1() {
    asm volatile("cp.async.wait_group 1;" ::: "memory");
}
__device__ __forceinline__ void ldmatrix_x4(uint32_t& r0, uint32_t& r1,
                                            uint32_t& r2, uint32_t& r3, uint32_t a) {
    asm volatile("ldmatrix.sync.aligned.m8n8.x4.shared.b16 {%0,%1,%2,%3}, [%4];"
                 : "=r"(r0), "=r"(r1), "=r"(r2), "=r"(r3) : "r"(a));
}
__device__ __forceinline__ void mma_f16(float* d, const uint32_t* a, const uint32_t* b) {
    asm volatile(
        "mma.sync.aligned.m16n8k16.row.col.f32.f16.f16.f32 "
        "{%0,%1,%2,%3}, {%4,%5,%6,%7}, {%8,%9}, {%0,%1,%2,%3};"
        : "+f"(d[0]), "+f"(d[1]), "+f"(d[2]), "+f"(d[3])
        : "r"(a[0]), "r"(a[1]), "r"(a[2]), "r"(a[3]), "r"(b[0]), "r"(b[1]));
}

__device__ __forceinline__ uint32_t pack_f16(__half a, __half b) {
    __half2 t{a, b};
    uint32_t r;
    memcpy(&r, &t, 4);
    return r;
}
__device__ __forceinline__ void split2(float v, __half& h, __half& l) {
    h = __float2half_rn(v);
    l = __float2half_rn(v - __half2float(h));
}

// ---------------------------------------------------------------------------
// Merged split kernel: one launch handles x, w1, w2 (w2 zero-padded to NPAD).
// ---------------------------------------------------------------------------
__global__ __launch_bounds__(256)
void split2_all_kernel(const float4* __restrict__ x,
                       const float4* __restrict__ w1,
                       const float4* __restrict__ w2,
                       __half* __restrict__ xh, __half* __restrict__ xl,
                       __half* __restrict__ w1h, __half* __restrict__ w1l,
                       __half* __restrict__ w2h, __half* __restrict__ w2l,
                       int n4x, int n4w1, int n4w2p) {
    int i = blockIdx.x * blockDim.x + threadIdx.x;
    float4 v;
    __half* dh;
    __half* dl;
    int di;
    if (i < n4x) {
        v = x[i];
        dh = xh; dl = xl; di = i;
    } else if (i < n4x + n4w1) {
        di = i - n4x;
        v = w1[di];
        dh = w1h; dl = w1l;
    } else if (i < n4x + n4w1 + n4w2p) {
        di = i - n4x - n4w1;
        int row = di >> 10;  // INPUT/4 = 1024 float4 per row
        v = (row < CLASSES) ? w2[di] : make_float4(0.f, 0.f, 0.f, 0.f);
        dh = w2h; dl = w2l;
    } else {
        return;
    }
    __half h0, h1, h2, h3, l0, l1, l2, l3;
    split2(v.x, h0, l0);
    split2(v.y, h1, l1);
    split2(v.z, h2, l2);
    split2(v.w, h3, l3);
    ((uint2*)dh)[di] = make_uint2(pack_f16(h0, h1), pack_f16(h2, h3));
    ((uint2*)dl)[di] = make_uint2(pack_f16(l0, l1), pack_f16(l2, l3));
}

// ---------------------------------------------------------------------------
// PERSISTENT pipelined mma.sync fp16 GEMM, 2-way split, 3 products, DUAL
// accumulators: acc <- hi*hi ; acc2 <- hi*lo + lo*hi  (lo*lo dropped).
// Grid = #SMs; each CTA walks tiles bid, bid+G, ... with a globally
// continuous cp.async pipeline (loader counter gi runs 2 stages ahead of
// compute counter gc across tile boundaries; epilogue overlaps in-flight
// loads). Inner loop identical to round-16 (128x128 tile, BK=64, 512 thr).
// Tile decode: tn = t % tilesN; tm = (t/tilesN) % tilesM; kz = t/(tilesN*tilesM).
// MODE 0: out = relu(C + bias), re-split to 2 fp16 arrays (ld = HIDDEN)
// MODE 1: out = C (+bias if kz==0) fp32 to plane kz of o_f32 (ld = NPAD)
// ---------------------------------------------------------------------------
template <int MODE>
__global__ __launch_bounds__(GTHREADS, 1)
void gemm_kernel(const __half* __restrict__ A0,
                 const __half* __restrict__ A1,
                 const __half* __restrict__ B0,
                 const __half* __restrict__ B1,
                 const float* __restrict__ bias, int biasN,
                 __half* __restrict__ o_hi,
                 __half* __restrict__ o_lo,
                 float* __restrict__ o_f32,
                 int tilesN, int tilesM, int niter, int ntiles) {
    extern __shared__ __align__(128) char smem[];
    const uint32_t smem_u = smem_u32(smem);

    const int tid = threadIdx.x;
    const int lane = tid & 31;
    const int wid = tid >> 5;       // 0..15
    const int warpRow = wid >> 2;   // 0..3 -> 32 rows each
    const int warpCol = wid & 3;    // 0..3 -> 32 cols each
    const int G = gridDim.x;
    const int bid = blockIdx.x;
    if (bid >= ntiles) return;

    constexpr size_t K2 = (size_t)KDIM * 2;

    // ---- loader state ----
    const int lrow = tid >> 3;      // 0..63
    const int lch = tid & 7;        // 0..7 (16B chunk within 128B row)
    const uint32_t sdst0 = lrow * STRIDE + lch * 16;
    const char* gp[4];

    auto set_ptrs = [&](int tile) {
        int tn = tile % tilesN;
        int rem = tile / tilesN;
        int tm = rem % tilesM;
        int tkz = rem / tilesM;
        int bMl = tm * BM, bNl = tn * BN;
        size_t koff = (size_t)tkz * niter * BK * 2;
        gp[0] = (const char*)A0 + (size_t)(bMl + lrow) * K2 + koff + lch * 16;
        gp[1] = (const char*)B0 + (size_t)(bNl + lrow) * K2 + koff + lch * 16;
        gp[2] = (const char*)A1 + (size_t)(bMl + lrow) * K2 + koff + lch * 16;
        gp[3] = (const char*)B1 + (size_t)(bNl + lrow) * K2 + koff + lch * 16;
    };

    int ld_tile = bid, ld_it = 0, ld_buf = 0;
    bool ld_active = true;
    set_ptrs(ld_tile);
    long long gi = 0, gc = 0;

    auto issue = [&]() {
        if (!ld_active) return;
        const uint32_t sb = smem_u + ld_buf * STAGE_B + sdst0;
        #pragma unroll
        for (int mc = 0; mc < 4; mc++) {
            const char* g = gp[mc];
            cp_async16(sb + mc * TILE_B, g);
            cp_async16(sb + mc * TILE_B + 64 * STRIDE, g + (size_t)64 * K2);
            gp[mc] = g + BK * 2;
        }
        cp_commit();
        gi++;
        ld_buf = (ld_buf + 1 == NSTAGES) ? 0 : ld_buf + 1;
        if (++ld_it == niter) {
            ld_it = 0;
            ld_tile += G;
            if (ld_tile < ntiles) set_ptrs(ld_tile);
            else ld_active = false;
        }
    };

    // ldmatrix per-lane address components
    const int rA = ((lane >> 3) & 1) * 8 + (lane & 7);
    const int cA = (lane >> 4);
    const int rB = (lane >> 4) * 8 + (lane & 7);
    const int cB = (lane >> 3) & 1;

    const int gr = lane >> 2;         // epilogue row within 8
    const int cc = (lane & 3) * 2;    // epilogue col pair

    // prologue: 2 stages
    issue();
    issue();

    int cbuf = 0;
    for (int tile = bid; tile < ntiles; tile += G) {
        // decode current tile for epilogue
        int tn = tile % tilesN;
        int rem = tile / tilesN;
        int tm = rem % tilesM;
        int kz = rem / tilesM;
        const int blockM = tm * BM;
        const int blockN = tn * BN;

        float acc[2][4][4];
        float acc2[2][4][4];
        #pragma unroll
        for (int mt = 0; mt < 2; mt++)
            #pragma unroll
            for (int nt = 0; nt < 4; nt++)
                #pragma unroll
                for (int e = 0; e < 4; e++) { acc[mt][nt][e] = 0.0f; acc2[mt][nt][e] = 0.0f; }

        for (int it = 0; it < niter; it++) {
            if (gi - gc >= 2) cp_wait1(); else cp_wait0();
            __syncthreads();
            issue();   // continuous pipeline: may belong to the NEXT tile

            const uint32_t stage = smem_u + cbuf * STAGE_B;
            #pragma unroll
            for (int kh = 0; kh < 4; kh++) {
                uint32_t aF[2][2][4];
                #pragma unroll
                for (int t = 0; t < 2; t++) {
                    const uint32_t Abase = stage + (2 * t) * TILE_B;
                    #pragma unroll
                    for (int mt = 0; mt < 2; mt++) {
                        uint32_t addr = Abase + (warpRow * 32 + mt * 16 + rA) * STRIDE +
                                        (kh * 2 + cA) * 16;
                        ldmatrix_x4(aF[t][mt][0], aF[t][mt][1], aF[t][mt][2], aF[t][mt][3], addr);
                    }
                }
                uint32_t bF[2][4][2];
                #pragma unroll
                for (int t = 0; t < 2; t++) {
                    const uint32_t Bbase = stage + (2 * t + 1) * TILE_B;
                    #pragma unroll
                    for (int pr = 0; pr < 2; pr++) {
                        uint32_t addr = Bbase + (warpCol * 32 + pr * 16 + rB) * STRIDE +
                                        (kh * 2 + cB) * 16;
                        uint32_t r0, r1, r2, r3;
                        ldmatrix_x4(r0, r1, r2, r3, addr);
                        bF[t][pr * 2 + 0][0] = r0; bF[t][pr * 2 + 0][1] = r1;
                        bF[t][pr * 2 + 1][0] = r2; bF[t][pr * 2 + 1][1] = r3;
                    }
                }
                #pragma unroll
                for (int mt = 0; mt < 2; mt++)
                    #pragma unroll
                    for (int nt = 0; nt < 4; nt++)
                        mma_f16(acc[mt][nt], aF[0][mt], bF[0][nt]);
                #pragma unroll
                for (int mt = 0; mt < 2; mt++)
                    #pragma unroll
                    for (int nt = 0; nt < 4; nt++)
                        mma_f16(acc2[mt][nt], aF[0][mt], bF[1][nt]);
                #pragma unroll
                for (int mt = 0; mt < 2; mt++)
                    #pragma unroll
                    for (int nt = 0; nt < 4; nt++)
                        mma_f16(acc2[mt][nt], aF[1][mt], bF[0][nt]);
            }
            gc++;
            cbuf = (cbuf + 1 == NSTAGES) ? 0 : cbuf + 1;
        }

        // ---- epilogue (registers + global only; overlaps in-flight loads) ----
        float* o_plane = (MODE == 1) ? o_f32 + (size_t)kz * BATCH * NPAD : nullptr;
        #pragma unroll
        for (int mt = 0; mt < 2; mt++) {
            #pragma unroll
            for (int nt = 0; nt < 4; nt++) {
                float d[4];
                #pragma unroll
                for (int e = 0; e < 4; e++) d[e] = acc[mt][nt][e] + acc2[mt][nt][e];
                const int col = blockN + warpCol * 32 + nt * 8 + cc;
                const int row0 = blockM + warpRow * 32 + mt * 16 + gr;
                float bv0, bv1;
                if (MODE == 0) {
                    bv0 = bias[col];
                    bv1 = bias[col + 1];
                } else {
                    bv0 = (kz == 0 && col < biasN) ? bias[col] : 0.0f;
                    bv1 = (kz == 0 && col + 1 < biasN) ? bias[col + 1] : 0.0f;
                }
                if (MODE == 0) {
                    #pragma unroll
                    for (int h = 0; h < 2; h++) {
                        const int row = row0 + h * 8;
                        float v0 = fmaxf(d[2 * h + 0] + bv0, 0.0f);
                        float v1 = fmaxf(d[2 * h + 1] + bv1, 0.0f);
                        __half h0, l0, h1, l1;
                        split2(v0, h0, l0);
                        split2(v1, h1, l1);
                        size_t off = (size_t)row * HIDDEN + col;
                        *(uint32_t*)(o_hi + off) = pack_f16(h0, h1);
                        *(uint32_t*)(o_lo + off) = pack_f16(l0, l1);
                    }
                } else {
                    #pragma unroll
                    for (int h = 0; h < 2; h++) {
                        const int row = row0 + h * 8;
                        float2 v;
                        v.x = d[2 * h + 0] + bv0;
                        v.y = d[2 * h + 1] + bv1;
                        *(float2*)(o_plane + (size_t)row * NPAD + col) = v;
                    }
                }
            }
        }
    }
}

// ---------------------------------------------------------------------------
// Row softmax over two split-K logits planes (summed on load)
// ---------------------------------------------------------------------------
__inline__ __device__ float warpMax(float v) {
    #pragma unroll
    for (int o = 16; o > 0; o >>= 1) v = fmaxf(v, __shfl_xor_sync(0xffffffffu, v, o));
    return v;
}
__inline__ __device__ float warpSum(float v) {
    #pragma unroll
    for (int o = 16; o > 0; o >>= 1) v += __shfl_xor_sync(0xffffffffu, v, o);
    return v;
}

__global__ __launch_bounds__(256)
void softmax_kernel(const float* __restrict__ logits0,
                    const float* __restrict__ logits1,
                    float* __restrict__ out) {
    const int row = blockIdx.x;
    const float* lp0 = logits0 + (size_t)row * NPAD;
    const float* lp1 = logits1 + (size_t)row * NPAD;
    float* op = out + (size_t)row * CLASSES;

    const int tid = threadIdx.x, lane = tid & 31, warp = tid >> 5;
    __shared__ float red[8];

    float v[4];
    int idx[4], cnt = 0;
    for (int i = tid; i < CLASSES; i += 256) {
        v[cnt] = lp0[i] + lp1[i];
        idx[cnt] = i;
        cnt++;
    }

    float m = -INFINITY;
    for (int t = 0; t < cnt; t++) m = fmaxf(m, v[t]);
    m = warpMax(m);
    if (lane == 0) red[warp] = m;
    __syncthreads();
    m = (lane < 8) ? red[lane] : -INFINITY;
    m = warpMax(m);
    m = __shfl_sync(0xffffffffu, m, 0);

    float s = 0.0f;
    for (int t = 0; t < cnt; t++) { v[t] = __expf(v[t] - m); s += v[t]; }
    s = warpSum(s);
    __syncthreads();
    if (lane == 0) red[warp] = s;
    __syncthreads();
    s = (lane < 8) ? red[lane] : 0.0f;
    s = warpSum(s);
    s = __shfl_sync(0xffffffffu, s, 0);

    const float inv = 1.0f / s;
    for (int t = 0; t < cnt; t++) op[idx[t]] = v[t] * inv;
}

// ---------------------------------------------------------------------------
// Host launch
// ---------------------------------------------------------------------------
extern "C" void kernel_launch(void* const* d_in, const int* in_sizes, int n_in,
                              void* d_out, int out_size) {
    const float* x  = (const float*)d_in[0];
    const float* w1 = (const float*)d_in[1];
    const float* b1 = (const float*)d_in[2];
    const float* w2 = (const float*)d_in[3];
    const float* b2 = (const float*)d_in[4];
    float* out = (float*)d_out;

    __half *xs, *w1s, *w2s, *hs;
    float* logits;
    cudaGetSymbolAddress((void**)&xs,  g_x_s);
    cudaGetSymbolAddress((void**)&w1s, g_w1_s);
    cudaGetSymbolAddress((void**)&w2s, g_w2_s);
    cudaGetSymbolAddress((void**)&hs,  g_h_s);
    cudaGetSymbolAddress((void**)&logits, g_logits);

    const size_t XN  = (size_t)BATCH * INPUT;
    const size_t W1N = (size_t)HIDDEN * INPUT;
    const size_t W2N = (size_t)NPAD * INPUT;
    const size_t HN  = (size_t)BATCH * HIDDEN;
    const size_t LN  = (size_t)BATCH * NPAD;

    __half* x_c[2]  = {xs, xs + XN};
    __half* w1_c[2] = {w1s, w1s + W1N};
    __half* w2_c[2] = {w2s, w2s + W2N};
    __half* h_c[2]  = {hs, hs + HN};

    int nsm = 148;
    cudaDeviceGetAttribute(&nsm, cudaDevAttrMultiProcessorCount, 0);

    // One merged split launch for x, w1, w2
    {
        int n4x = (int)(XN / 4);
        int n4w1 = (int)(W1N / 4);
        int n4w2p = (int)(W2N / 4);
        int total = n4x + n4w1 + n4w2p;
        split2_all_kernel<<<(total + 255) / 256, 256>>>(
            (const float4*)x, (const float4*)w1, (const float4*)w2,
            x_c[0], x_c[1], w1_c[0], w1_c[1], w2_c[0], w2_c[1],
            n4x, n4w1, n4w2p);
    }

    cudaFuncSetAttribute(gemm_kernel<0>, cudaFuncAttributeMaxDynamicSharedMemorySize, DYN_SMEM);
    cudaFuncSetAttribute(gemm_kernel<1>, cudaFuncAttributeMaxDynamicSharedMemorySize, DYN_SMEM);

    // GEMM1: hidden = relu(x @ w1^T + b1); persistent grid, tiles 32x64x1,
    // niter=64
    {
        int tilesN = HIDDEN / BN, tilesM = BATCH / BM;
        int ntiles = tilesN * tilesM;               // 2048
        gemm_kernel<0><<<nsm, GTHREADS, DYN_SMEM>>>(
            x_c[0], x_c[1], w1_c[0], w1_c[1],
            b1, HIDDEN, h_c[0], h_c[1], nullptr,
            tilesN, tilesM, KDIM / BK, ntiles);
    }
    // GEMM2: logits (split-K=2 planes); persistent grid, tiles 8x64x2,
    // niter=32
    {
        int tilesN = NPAD / BN, tilesM = BATCH / BM;
        int ntiles = tilesN * tilesM * 2;           // 1024
        gemm_kernel<1><<<nsm, GTHREADS, DYN_SMEM>>>(
            h_c[0], h_c[1], w2_c[0], w2_c[1],
            b2, CLASSES, nullptr, nullptr, logits,
            tilesN, tilesM, (KDIM / 2) / BK, ntiles);
    }
    // Softmax over summed planes
    softmax_kernel<<<BATCH, 256>>>(logits, logits + LN, out);
}